// round 1
// baseline (speedup 1.0000x reference)
#include <cuda_runtime.h>
#include <cuda_bf16.h>

// ---------------------------------------------------------------------------
// Problem constants
// ---------------------------------------------------------------------------
#define BATCH   4
#define SEQ     4096
#define DMODEL  1024
#define NHEADS  8
#define HDIM    64
#define STATE   512            // NHEADS*HDIM
#define PROJW   2048           // 4*STATE
#define ROWS    (BATCH*SEQ)    // 16384

// ---------------------------------------------------------------------------
// Scratch (device globals -- no runtime allocation allowed)
// ---------------------------------------------------------------------------
__device__ float g_proj[(size_t)ROWS * PROJW];   // 128 MB: [xi_raw | xf | xr | g]
__device__ float g_xi  [(size_t)ROWS * STATE];   // 32 MB: conv+silu output
__device__ float g_y   [(size_t)ROWS * STATE];   // 32 MB: recurrence output
__device__ float g_yn  [(size_t)ROWS * STATE];   // 32 MB: gated + rmsnormed

// ---------------------------------------------------------------------------
// Packed f32x2 helpers (FFMA2 is only reachable via PTX fma.rn.f32x2)
// ---------------------------------------------------------------------------
__device__ __forceinline__ unsigned long long pk2(float lo, float hi) {
    unsigned long long r;
    asm("mov.b64 %0, {%1, %2};" : "=l"(r) : "f"(lo), "f"(hi));
    return r;
}
__device__ __forceinline__ void fma2(unsigned long long& d,
                                     unsigned long long a,
                                     unsigned long long b) {
    asm("fma.rn.f32x2 %0, %1, %2, %0;" : "+l"(d) : "l"(a), "l"(b));
}
__device__ __forceinline__ unsigned long long add2(unsigned long long a,
                                                   unsigned long long b) {
    unsigned long long d;
    asm("add.rn.f32x2 %0, %1, %2;" : "=l"(d) : "l"(a), "l"(b));
    return d;
}
__device__ __forceinline__ float hadd2(unsigned long long v) {
    float a, b;
    asm("mov.b64 {%0, %1}, %2;" : "=f"(a), "=f"(b) : "l"(v));
    return a + b;
}
__device__ __forceinline__ void unpk2(unsigned long long v, float& lo, float& hi) {
    asm("mov.b64 {%0, %1}, %2;" : "=f"(lo), "=f"(hi) : "l"(v));
}

__device__ __forceinline__ float fsigmoid(float x) {
    return __fdividef(1.0f, 1.0f + __expf(-x));
}
__device__ __forceinline__ float ftanh(float x) {
    // tanh(x) = 1 - 2/(exp(2x)+1); saturates correctly at +-inf
    float e = __expf(2.0f * x);
    return 1.0f - __fdividef(2.0f, e + 1.0f);
}

// ---------------------------------------------------------------------------
// SGEMM (NT): C[m,n] = sum_k A[m,K]*B[n,K].  M%128==0, N%128==0, K%8==0.
// 128x128 tile, BK=8, 256 threads, 8x8 micro-tile with f32x2-packed columns.
// ---------------------------------------------------------------------------
__global__ void __launch_bounds__(256)
sgemm_nt(const float* __restrict__ A, const float* __restrict__ Bm,
         float* __restrict__ C, int M, int N, int K)
{
    __shared__ __align__(16) float As[8][132];
    __shared__ __align__(16) float Bs[8][132];

    const int tid = threadIdx.x;
    const int bm  = blockIdx.y * 128;
    const int bn  = blockIdx.x * 128;

    const int lr = tid >> 1;          // 0..127 tile row for global load
    const int lc = (tid & 1) << 2;    // 0 or 4 (k offset)
    const float* Ag = A  + (size_t)(bm + lr) * K + lc;
    const float* Bg = Bm + (size_t)(bn + lr) * K + lc;

    const int warp = tid >> 5, lane = tid & 31;
    const int tn = (warp & 1) * 64 + (lane & 7) * 8;   // 2 warps across n
    const int tm = (warp >> 1) * 32 + (lane >> 3) * 8; // 4 warps down m

    unsigned long long acc[8][4];
#pragma unroll
    for (int i = 0; i < 8; i++)
#pragma unroll
        for (int j = 0; j < 4; j++) acc[i][j] = 0ull;

    float4 av = *(const float4*)Ag;
    float4 bv = *(const float4*)Bg;

    for (int k0 = 0; k0 < K; k0 += 8) {
        __syncthreads();
        As[lc + 0][lr] = av.x; As[lc + 1][lr] = av.y;
        As[lc + 2][lr] = av.z; As[lc + 3][lr] = av.w;
        Bs[lc + 0][lr] = bv.x; Bs[lc + 1][lr] = bv.y;
        Bs[lc + 2][lr] = bv.z; Bs[lc + 3][lr] = bv.w;
        __syncthreads();
        if (k0 + 8 < K) {
            av = *(const float4*)(Ag + k0 + 8);
            bv = *(const float4*)(Bg + k0 + 8);
        }
#pragma unroll
        for (int kk = 0; kk < 8; kk++) {
            float4 a0 = *(const float4*)&As[kk][tm];
            float4 a1 = *(const float4*)&As[kk][tm + 4];
            ulonglong2 b01 = *(const ulonglong2*)&Bs[kk][tn];
            ulonglong2 b23 = *(const ulonglong2*)&Bs[kk][tn + 4];
            unsigned long long a2[8] = {
                pk2(a0.x, a0.x), pk2(a0.y, a0.y), pk2(a0.z, a0.z), pk2(a0.w, a0.w),
                pk2(a1.x, a1.x), pk2(a1.y, a1.y), pk2(a1.z, a1.z), pk2(a1.w, a1.w)
            };
            unsigned long long bb[4] = { b01.x, b01.y, b23.x, b23.y };
#pragma unroll
            for (int i = 0; i < 8; i++)
#pragma unroll
                for (int j = 0; j < 4; j++)
                    fma2(acc[i][j], a2[i], bb[j]);
        }
    }

#pragma unroll
    for (int i = 0; i < 8; i++) {
        float* Crow = C + (size_t)(bm + tm + i) * N + bn + tn;
#pragma unroll
        for (int j = 0; j < 4; j++) {
            float lo, hi;
            unpk2(acc[i][j], lo, hi);
            *(float2*)(Crow + 2 * j) = make_float2(lo, hi);
        }
    }
}

// ---------------------------------------------------------------------------
// Depthwise causal conv (K=4) over xi (= proj[:, :512]) + SiLU -> g_xi
// ---------------------------------------------------------------------------
__global__ void conv_silu_kernel(const float* __restrict__ proj,
                                 const float* __restrict__ cw,
                                 float* __restrict__ xi)
{
    int idx = blockIdx.x * 256 + threadIdx.x;           // over ROWS*STATE
    if (idx >= ROWS * STATE) return;
    int c   = idx & (STATE - 1);
    int row = idx >> 9;
    int s   = row & (SEQ - 1);
    float acc = 0.0f;
#pragma unroll
    for (int kk = 0; kk < 4; kk++) {
        int d = kk - 3;
        if (s + d >= 0)
            acc += cw[c * 4 + kk] * proj[(size_t)(row + d) * PROJW + c];
    }
    xi[idx] = acc * fsigmoid(acc);
}

// ---------------------------------------------------------------------------
// Sequential recurrence. Grid = 32 blocks (b*8+head), 128 threads.
//   warps 0-1 (tid<64): f-gate dot, z matvec, h update, y store
//   warps 2-3          : r-gate dot, publish h*r
// Weight columns (Wf|Wr, and W for f-threads) are register-resident, packed
// over row pairs for f32x2. h lives in shared; 2 syncthreads per step.
// ---------------------------------------------------------------------------
__global__ void __launch_bounds__(128, 1)
scan_kernel(const float* __restrict__ proj, const float* __restrict__ xi_in,
            const float* __restrict__ sw, float* __restrict__ y)
{
    const int tid  = threadIdx.x;
    const int k    = tid & 63;
    const bool isf = tid < 64;
    const int head = blockIdx.x & 7;
    const int b    = blockIdx.x >> 3;

    __shared__ __align__(16) float h_sh[64];
    __shared__ __align__(16) float hr_sh[64];

    // Register weight columns (column k of each 64x64 matrix, packed by rows)
    unsigned long long wg[32];  // Wf (f-threads) or Wr (r-threads)
    unsigned long long wz[32];  // W  (f-threads only)
    {
        const int gidx = isf ? (NHEADS + head) : (2 * NHEADS + head);
        const float* base = sw + (size_t)gidx * 64 * 64 + k;
#pragma unroll
        for (int i = 0; i < 32; i++)
            wg[i] = pk2(base[(2 * i) * 64], base[(2 * i + 1) * 64]);
        if (isf) {
            const float* bz = sw + (size_t)head * 64 * 64 + k;
#pragma unroll
            for (int i = 0; i < 32; i++)
                wz[i] = pk2(bz[(2 * i) * 64], bz[(2 * i + 1) * 64]);
        }
    }

    if (tid < 64) h_sh[tid] = 0.0f;
    __syncthreads();

    const float* xg_ptr = proj + (size_t)b * SEQ * PROJW
                          + (isf ? STATE : 2 * STATE) + head * HDIM + k;
    const float* xi_ptr = xi_in + (size_t)b * SEQ * STATE + head * HDIM + k;
    float* y_ptr = y + (size_t)b * SEQ * STATE + head * HDIM + k;

    // Prefetch 4 steps deep
    float xg_buf[4], xi_buf[4];
#pragma unroll
    for (int j = 0; j < 4; j++) {
        xg_buf[j] = xg_ptr[(size_t)j * PROJW];
        xi_buf[j] = isf ? xi_ptr[(size_t)j * STATE] : 0.0f;
    }

    for (int t0 = 0; t0 < SEQ; t0 += 4) {
#pragma unroll
        for (int j = 0; j < 4; j++) {
            const int t = t0 + j;
            const float xg  = xg_buf[j];
            const float xiv = xi_buf[j];
            int tp = t + 4; if (tp > SEQ - 1) tp = SEQ - 1;
            xg_buf[j] = xg_ptr[(size_t)tp * PROJW];
            if (isf) xi_buf[j] = xi_ptr[(size_t)tp * STATE];

            // phase 1: gate dot over previous h (packed pairs, broadcast LDS)
            unsigned long long a0 = 0ull, a1 = 0ull;
#pragma unroll
            for (int i = 0; i < 16; i++) {
                unsigned long long h2a =
                    *reinterpret_cast<const unsigned long long*>(h_sh + 4 * i);
                unsigned long long h2b =
                    *reinterpret_cast<const unsigned long long*>(h_sh + 4 * i + 2);
                fma2(a0, h2a, wg[2 * i]);
                fma2(a1, h2b, wg[2 * i + 1]);
            }
            const float gate = fsigmoid(hadd2(add2(a0, a1)) + xg);
            const float hk = h_sh[k];
            if (!isf) hr_sh[k] = hk * gate;     // r-path publishes h*r
            __syncthreads();                     // hr visible

            if (isf) {
                // phase 2: z matvec over h*r
                unsigned long long z0 = 0ull, z1 = 0ull;
#pragma unroll
                for (int i = 0; i < 16; i++) {
                    unsigned long long h2a =
                        *reinterpret_cast<const unsigned long long*>(hr_sh + 4 * i);
                    unsigned long long h2b =
                        *reinterpret_cast<const unsigned long long*>(hr_sh + 4 * i + 2);
                    fma2(z0, h2a, wz[2 * i]);
                    fma2(z1, h2b, wz[2 * i + 1]);
                }
                const float z  = ftanh(hadd2(add2(z0, z1)) + xiv);
                const float hn = gate * hk + (1.0f - gate) * z;
                h_sh[k] = hn;
                y_ptr[(size_t)t * STATE] = hn;
            }
            __syncthreads();                     // new h visible
        }
    }
}

// ---------------------------------------------------------------------------
// Epilogue: v = y * silu(g); rmsnorm over 512; * norm_w -> g_yn
// One block per row, 128 threads x 4 columns.
// ---------------------------------------------------------------------------
__global__ void __launch_bounds__(128)
epilogue_kernel(const float* __restrict__ y, const float* __restrict__ proj,
                const float* __restrict__ norm_w, float* __restrict__ yn)
{
    const int row = blockIdx.x;
    const int tid = threadIdx.x;
    const float* yr = y   + (size_t)row * STATE;
    const float* gr = proj + (size_t)row * PROJW + 3 * STATE;

    float v[4];
    float ss = 0.0f;
#pragma unroll
    for (int q = 0; q < 4; q++) {
        int c = tid + q * 128;
        float g = gr[c];
        float val = yr[c] * g * fsigmoid(g);
        v[q] = val;
        ss += val * val;
    }
#pragma unroll
    for (int off = 16; off > 0; off >>= 1)
        ss += __shfl_xor_sync(0xffffffffu, ss, off);
    __shared__ float red[4];
    if ((tid & 31) == 0) red[tid >> 5] = ss;
    __syncthreads();
    float tot = red[0] + red[1] + red[2] + red[3];
    float scale = rsqrtf(tot * (1.0f / 512.0f) + 1e-6f);
#pragma unroll
    for (int q = 0; q < 4; q++) {
        int c = tid + q * 128;
        yn[(size_t)row * STATE + c] = v[q] * scale * norm_w[c];
    }
}

// ---------------------------------------------------------------------------
// Launch
// ---------------------------------------------------------------------------
extern "C" void kernel_launch(void* const* d_in, const int* in_sizes, int n_in,
                              void* d_out, int out_size)
{
    const float* x      = (const float*)d_in[0];
    const float* w_in   = (const float*)d_in[1];
    const float* conv_w = (const float*)d_in[2];
    const float* sw     = (const float*)d_in[3];
    const float* norm_w = (const float*)d_in[4];
    const float* w_out  = (const float*)d_in[5];
    float* out = (float*)d_out;

    float *proj, *xi, *y, *yn;
    cudaGetSymbolAddress((void**)&proj, g_proj);
    cudaGetSymbolAddress((void**)&xi,   g_xi);
    cudaGetSymbolAddress((void**)&y,    g_y);
    cudaGetSymbolAddress((void**)&yn,   g_yn);

    // 1. proj = x @ w_in^T   (16384 x 2048 x 1024)
    {
        dim3 grid(PROJW / 128, ROWS / 128);
        sgemm_nt<<<grid, 256>>>(x, w_in, proj, ROWS, PROJW, DMODEL);
    }
    // 2. depthwise conv + silu -> xi
    conv_silu_kernel<<<(ROWS * STATE) / 256, 256>>>(proj, conv_w, xi);
    // 3. sequential recurrence -> y
    scan_kernel<<<BATCH * NHEADS, 128>>>(proj, xi, sw, y);
    // 4. gate + rmsnorm -> yn
    epilogue_kernel<<<ROWS, 128>>>(y, proj, norm_w, yn);
    // 5. out = yn @ w_out^T  (16384 x 1024 x 512)
    {
        dim3 grid(DMODEL / 128, ROWS / 128);
        sgemm_nt<<<grid, 256>>>(yn, w_out, out, ROWS, DMODEL, STATE);
    }
}

// round 2
// speedup vs baseline: 1.3714x; 1.3714x over previous
#include <cuda_runtime.h>
#include <cuda_bf16.h>
#include <cstdint>

// ---------------------------------------------------------------------------
// Problem constants
// ---------------------------------------------------------------------------
#define BATCH   4
#define SEQ     4096
#define DMODEL  1024
#define NHEADS  8
#define HDIM    64
#define STATE   512            // NHEADS*HDIM
#define PROJW   2048           // 4*STATE
#define ROWS    (BATCH*SEQ)    // 16384

// ---------------------------------------------------------------------------
// Scratch (device globals -- no runtime allocation allowed)
// ---------------------------------------------------------------------------
__device__ float g_proj[(size_t)ROWS * PROJW];   // 128 MB: [xi_raw | xf | xr | g]
__device__ float g_xi  [(size_t)ROWS * STATE];   // 32 MB: conv+silu output
__device__ float g_y   [(size_t)ROWS * STATE];   // 32 MB: recurrence output
__device__ float g_yn  [(size_t)ROWS * STATE];   // 32 MB: gated + rmsnormed

// ---------------------------------------------------------------------------
// Packed f32x2 helpers (for the scan kernel)
// ---------------------------------------------------------------------------
__device__ __forceinline__ unsigned long long pk2(float lo, float hi) {
    unsigned long long r;
    asm("mov.b64 %0, {%1, %2};" : "=l"(r) : "f"(lo), "f"(hi));
    return r;
}
__device__ __forceinline__ void fma2(unsigned long long& d,
                                     unsigned long long a,
                                     unsigned long long b) {
    asm("fma.rn.f32x2 %0, %1, %2, %0;" : "+l"(d) : "l"(a), "l"(b));
}
__device__ __forceinline__ unsigned long long add2(unsigned long long a,
                                                   unsigned long long b) {
    unsigned long long d;
    asm("add.rn.f32x2 %0, %1, %2;" : "=l"(d) : "l"(a), "l"(b));
    return d;
}
__device__ __forceinline__ float hadd2(unsigned long long v) {
    float a, b;
    asm("mov.b64 {%0, %1}, %2;" : "=f"(a), "=f"(b) : "l"(v));
    return a + b;
}

__device__ __forceinline__ float fsigmoid(float x) {
    return __fdividef(1.0f, 1.0f + __expf(-x));
}
__device__ __forceinline__ float ftanh(float x) {
    float e = __expf(2.0f * x);
    return 1.0f - __fdividef(2.0f, e + 1.0f);
}
__device__ __forceinline__ uint32_t f2tf(float f) {
    uint32_t u;
    asm("cvt.rna.tf32.f32 %0, %1;" : "=r"(u) : "f"(f));
    return u;
}

// ---------------------------------------------------------------------------
// TF32 tensor-core GEMM (NT): C[m,n] = sum_k A[m,K]*B[n,K]
// Block 128x128, 4 warps (64x64 each), BK=16 double-buffered.
// A smem [16][136] (k-major, pad->conflict-free frags & stores)
// B smem [128][20]  (n-major, pad->conflict-free frags & stores)
// ---------------------------------------------------------------------------
__device__ __forceinline__ void mma_tf32(float* c, const uint32_t* a,
                                         const uint32_t* b) {
    asm volatile(
        "mma.sync.aligned.m16n8k8.row.col.f32.tf32.tf32.f32 "
        "{%0,%1,%2,%3}, {%4,%5,%6,%7}, {%8,%9}, {%0,%1,%2,%3};\n"
        : "+f"(c[0]), "+f"(c[1]), "+f"(c[2]), "+f"(c[3])
        : "r"(a[0]), "r"(a[1]), "r"(a[2]), "r"(a[3]), "r"(b[0]), "r"(b[1]));
}

__global__ void __launch_bounds__(128)
tf32_gemm_nt(const float* __restrict__ A, const float* __restrict__ Bm,
             float* __restrict__ C, int M, int N, int K)
{
    __shared__ uint32_t As[2][16][136];
    __shared__ uint32_t Bs[2][128][20];

    const int tid   = threadIdx.x;
    const int lane  = tid & 31;
    const int warp  = tid >> 5;
    const int group = lane >> 2;
    const int tig   = lane & 3;
    const int bm = blockIdx.y * 128;
    const int bn = blockIdx.x * 128;
    const int wm = (warp >> 1) * 64;
    const int wn = (warp & 1) * 64;

    const float* Ag = A  + (size_t)(bm + tid) * K;
    const float* Bg = Bm + (size_t)(bn + tid) * K;

    float c[4][8][4];
#pragma unroll
    for (int mt = 0; mt < 4; mt++)
#pragma unroll
        for (int nt = 0; nt < 8; nt++)
#pragma unroll
            for (int q = 0; q < 4; q++) c[mt][nt][q] = 0.0f;

    float4 va[4], vb[4];
#pragma unroll
    for (int i = 0; i < 4; i++) {
        va[i] = *(const float4*)(Ag + 4 * i);
        vb[i] = *(const float4*)(Bg + 4 * i);
    }
    // stage tile 0 into buffer 0
#pragma unroll
    for (int i = 0; i < 4; i++) {
        As[0][4 * i + 0][tid] = f2tf(va[i].x);
        As[0][4 * i + 1][tid] = f2tf(va[i].y);
        As[0][4 * i + 2][tid] = f2tf(va[i].z);
        As[0][4 * i + 3][tid] = f2tf(va[i].w);
        uint4 t;
        t.x = f2tf(vb[i].x); t.y = f2tf(vb[i].y);
        t.z = f2tf(vb[i].z); t.w = f2tf(vb[i].w);
        *(uint4*)&Bs[0][tid][4 * i] = t;
    }
    __syncthreads();

    int buf = 0;
    for (int k0 = 0; k0 < K; k0 += 16) {
        const bool more = (k0 + 16 < K);
        if (more) {
#pragma unroll
            for (int i = 0; i < 4; i++) {
                va[i] = *(const float4*)(Ag + k0 + 16 + 4 * i);
                vb[i] = *(const float4*)(Bg + k0 + 16 + 4 * i);
            }
        }
#pragma unroll
        for (int ks = 0; ks < 2; ks++) {
            const int kk = ks * 8;
            uint32_t a[4][4], b[8][2];
#pragma unroll
            for (int mt = 0; mt < 4; mt++) {
                int m = wm + mt * 16 + group;
                a[mt][0] = As[buf][kk + tig][m];
                a[mt][1] = As[buf][kk + tig][m + 8];
                a[mt][2] = As[buf][kk + tig + 4][m];
                a[mt][3] = As[buf][kk + tig + 4][m + 8];
            }
#pragma unroll
            for (int nt = 0; nt < 8; nt++) {
                int n = wn + nt * 8 + group;
                b[nt][0] = Bs[buf][n][kk + tig];
                b[nt][1] = Bs[buf][n][kk + tig + 4];
            }
#pragma unroll
            for (int mt = 0; mt < 4; mt++)
#pragma unroll
                for (int nt = 0; nt < 8; nt++)
                    mma_tf32(c[mt][nt], a[mt], b[nt]);
        }
        if (more) {
            buf ^= 1;
#pragma unroll
            for (int i = 0; i < 4; i++) {
                As[buf][4 * i + 0][tid] = f2tf(va[i].x);
                As[buf][4 * i + 1][tid] = f2tf(va[i].y);
                As[buf][4 * i + 2][tid] = f2tf(va[i].z);
                As[buf][4 * i + 3][tid] = f2tf(va[i].w);
                uint4 t;
                t.x = f2tf(vb[i].x); t.y = f2tf(vb[i].y);
                t.z = f2tf(vb[i].z); t.w = f2tf(vb[i].w);
                *(uint4*)&Bs[buf][tid][4 * i] = t;
            }
            __syncthreads();
        }
    }

#pragma unroll
    for (int mt = 0; mt < 4; mt++) {
        const int m0 = bm + wm + mt * 16 + group;
#pragma unroll
        for (int nt = 0; nt < 8; nt++) {
            const int n0 = bn + wn + nt * 8 + 2 * tig;
            *(float2*)(C + (size_t)m0 * N + n0) =
                make_float2(c[mt][nt][0], c[mt][nt][1]);
            *(float2*)(C + (size_t)(m0 + 8) * N + n0) =
                make_float2(c[mt][nt][2], c[mt][nt][3]);
        }
    }
}

// ---------------------------------------------------------------------------
// Depthwise causal conv (K=4) over xi (= proj[:, :512]) + SiLU -> g_xi
// ---------------------------------------------------------------------------
__global__ void conv_silu_kernel(const float* __restrict__ proj,
                                 const float* __restrict__ cw,
                                 float* __restrict__ xi)
{
    int idx = blockIdx.x * 256 + threadIdx.x;           // over ROWS*STATE
    if (idx >= ROWS * STATE) return;
    int c   = idx & (STATE - 1);
    int row = idx >> 9;
    int s   = row & (SEQ - 1);
    float acc = 0.0f;
#pragma unroll
    for (int kk = 0; kk < 4; kk++) {
        int d = kk - 3;
        if (s + d >= 0)
            acc += cw[c * 4 + kk] * proj[(size_t)(row + d) * PROJW + c];
    }
    xi[idx] = acc * fsigmoid(acc);
}

// ---------------------------------------------------------------------------
// Sequential recurrence. Grid = 32 blocks (b*8+head), 128 threads.
// ---------------------------------------------------------------------------
__global__ void __launch_bounds__(128, 1)
scan_kernel(const float* __restrict__ proj, const float* __restrict__ xi_in,
            const float* __restrict__ sw, float* __restrict__ y)
{
    const int tid  = threadIdx.x;
    const int k    = tid & 63;
    const bool isf = tid < 64;
    const int head = blockIdx.x & 7;
    const int b    = blockIdx.x >> 3;

    __shared__ __align__(16) float h_sh[64];
    __shared__ __align__(16) float hr_sh[64];

    unsigned long long wg[32];  // Wf (f-threads) or Wr (r-threads)
    unsigned long long wz[32];  // W  (f-threads only)
    {
        const int gidx = isf ? (NHEADS + head) : (2 * NHEADS + head);
        const float* base = sw + (size_t)gidx * 64 * 64 + k;
#pragma unroll
        for (int i = 0; i < 32; i++)
            wg[i] = pk2(base[(2 * i) * 64], base[(2 * i + 1) * 64]);
        if (isf) {
            const float* bz = sw + (size_t)head * 64 * 64 + k;
#pragma unroll
            for (int i = 0; i < 32; i++)
                wz[i] = pk2(bz[(2 * i) * 64], bz[(2 * i + 1) * 64]);
        }
    }

    if (tid < 64) h_sh[tid] = 0.0f;
    __syncthreads();

    const float* xg_ptr = proj + (size_t)b * SEQ * PROJW
                          + (isf ? STATE : 2 * STATE) + head * HDIM + k;
    const float* xi_ptr = xi_in + (size_t)b * SEQ * STATE + head * HDIM + k;
    float* y_ptr = y + (size_t)b * SEQ * STATE + head * HDIM + k;

    float xg_buf[4], xi_buf[4];
#pragma unroll
    for (int j = 0; j < 4; j++) {
        xg_buf[j] = xg_ptr[(size_t)j * PROJW];
        xi_buf[j] = isf ? xi_ptr[(size_t)j * STATE] : 0.0f;
    }

    for (int t0 = 0; t0 < SEQ; t0 += 4) {
#pragma unroll
        for (int j = 0; j < 4; j++) {
            const int t = t0 + j;
            const float xg  = xg_buf[j];
            const float xiv = xi_buf[j];
            int tp = t + 4; if (tp > SEQ - 1) tp = SEQ - 1;
            xg_buf[j] = xg_ptr[(size_t)tp * PROJW];
            if (isf) xi_buf[j] = xi_ptr[(size_t)tp * STATE];

            unsigned long long a0 = 0ull, a1 = 0ull;
#pragma unroll
            for (int i = 0; i < 16; i++) {
                unsigned long long h2a =
                    *reinterpret_cast<const unsigned long long*>(h_sh + 4 * i);
                unsigned long long h2b =
                    *reinterpret_cast<const unsigned long long*>(h_sh + 4 * i + 2);
                fma2(a0, h2a, wg[2 * i]);
                fma2(a1, h2b, wg[2 * i + 1]);
            }
            const float gate = fsigmoid(hadd2(add2(a0, a1)) + xg);
            const float hk = h_sh[k];
            if (!isf) hr_sh[k] = hk * gate;
            __syncthreads();

            if (isf) {
                unsigned long long z0 = 0ull, z1 = 0ull;
#pragma unroll
                for (int i = 0; i < 16; i++) {
                    unsigned long long h2a =
                        *reinterpret_cast<const unsigned long long*>(hr_sh + 4 * i);
                    unsigned long long h2b =
                        *reinterpret_cast<const unsigned long long*>(hr_sh + 4 * i + 2);
                    fma2(z0, h2a, wz[2 * i]);
                    fma2(z1, h2b, wz[2 * i + 1]);
                }
                const float z  = ftanh(hadd2(add2(z0, z1)) + xiv);
                const float hn = gate * hk + (1.0f - gate) * z;
                h_sh[k] = hn;
                y_ptr[(size_t)t * STATE] = hn;
            }
            __syncthreads();
        }
    }
}

// ---------------------------------------------------------------------------
// Epilogue: v = y * silu(g); rmsnorm over 512; * norm_w -> g_yn
// ---------------------------------------------------------------------------
__global__ void __launch_bounds__(128)
epilogue_kernel(const float* __restrict__ y, const float* __restrict__ proj,
                const float* __restrict__ norm_w, float* __restrict__ yn)
{
    const int row = blockIdx.x;
    const int tid = threadIdx.x;
    const float* yr = y    + (size_t)row * STATE;
    const float* gr = proj + (size_t)row * PROJW + 3 * STATE;

    float v[4];
    float ss = 0.0f;
#pragma unroll
    for (int q = 0; q < 4; q++) {
        int c = tid + q * 128;
        float g = gr[c];
        float val = yr[c] * g * fsigmoid(g);
        v[q] = val;
        ss += val * val;
    }
#pragma unroll
    for (int off = 16; off > 0; off >>= 1)
        ss += __shfl_xor_sync(0xffffffffu, ss, off);
    __shared__ float red[4];
    if ((tid & 31) == 0) red[tid >> 5] = ss;
    __syncthreads();
    float tot = red[0] + red[1] + red[2] + red[3];
    float scale = rsqrtf(tot * (1.0f / 512.0f) + 1e-6f);
#pragma unroll
    for (int q = 0; q < 4; q++) {
        int c = tid + q * 128;
        yn[(size_t)row * STATE + c] = v[q] * scale * norm_w[c];
    }
}

// ---------------------------------------------------------------------------
// Launch
// ---------------------------------------------------------------------------
extern "C" void kernel_launch(void* const* d_in, const int* in_sizes, int n_in,
                              void* d_out, int out_size)
{
    const float* x      = (const float*)d_in[0];
    const float* w_in   = (const float*)d_in[1];
    const float* conv_w = (const float*)d_in[2];
    const float* sw     = (const float*)d_in[3];
    const float* norm_w = (const float*)d_in[4];
    const float* w_out  = (const float*)d_in[5];
    float* out = (float*)d_out;

    float *proj, *xi, *y, *yn;
    cudaGetSymbolAddress((void**)&proj, g_proj);
    cudaGetSymbolAddress((void**)&xi,   g_xi);
    cudaGetSymbolAddress((void**)&y,    g_y);
    cudaGetSymbolAddress((void**)&yn,   g_yn);

    // 1. proj = x @ w_in^T   (16384 x 2048 x 1024), TF32 tensor cores
    {
        dim3 grid(PROJW / 128, ROWS / 128);
        tf32_gemm_nt<<<grid, 128>>>(x, w_in, proj, ROWS, PROJW, DMODEL);
    }
    // 2. depthwise conv + silu -> xi
    conv_silu_kernel<<<(ROWS * STATE) / 256, 256>>>(proj, conv_w, xi);
    // 3. sequential recurrence -> y
    scan_kernel<<<BATCH * NHEADS, 128>>>(proj, xi, sw, y);
    // 4. gate + rmsnorm -> yn
    epilogue_kernel<<<ROWS, 128>>>(y, proj, norm_w, yn);
    // 5. out = yn @ w_out^T  (16384 x 1024 x 512), TF32 tensor cores
    {
        dim3 grid(DMODEL / 128, ROWS / 128);
        tf32_gemm_nt<<<grid, 128>>>(yn, w_out, out, ROWS, DMODEL, STATE);
    }
}

// round 3
// speedup vs baseline: 1.5609x; 1.1382x over previous
#include <cuda_runtime.h>
#include <cuda_bf16.h>
#include <cstdint>

// ---------------------------------------------------------------------------
// Problem constants
// ---------------------------------------------------------------------------
#define BATCH   4
#define SEQ     4096
#define DMODEL  1024
#define NHEADS  8
#define HDIM    64
#define STATE   512            // NHEADS*HDIM
#define PROJW   2048           // 4*STATE
#define ROWS    (BATCH*SEQ)    // 16384

// ---------------------------------------------------------------------------
// Scratch (device globals -- no runtime allocation allowed)
// ---------------------------------------------------------------------------
__device__ float g_proj[(size_t)ROWS * PROJW];   // [xi_raw | xf | xr | g]
__device__ float g_xi  [(size_t)ROWS * STATE];   // conv+silu output
__device__ float g_y   [(size_t)ROWS * STATE];   // recurrence output
__device__ float g_yn  [(size_t)ROWS * STATE];   // gated + rmsnormed

// ---------------------------------------------------------------------------
// Packed f32x2 helpers
// ---------------------------------------------------------------------------
__device__ __forceinline__ unsigned long long pk2(float lo, float hi) {
    unsigned long long r;
    asm("mov.b64 %0, {%1, %2};" : "=l"(r) : "f"(lo), "f"(hi));
    return r;
}
__device__ __forceinline__ void fma2(unsigned long long& d,
                                     unsigned long long a,
                                     unsigned long long b) {
    asm("fma.rn.f32x2 %0, %1, %2, %0;" : "+l"(d) : "l"(a), "l"(b));
}
__device__ __forceinline__ unsigned long long add2(unsigned long long a,
                                                   unsigned long long b) {
    unsigned long long d;
    asm("add.rn.f32x2 %0, %1, %2;" : "=l"(d) : "l"(a), "l"(b));
    return d;
}
__device__ __forceinline__ float hadd2(unsigned long long v) {
    float a, b;
    asm("mov.b64 {%0, %1}, %2;" : "=f"(a), "=f"(b) : "l"(v));
    return a + b;
}

__device__ __forceinline__ float fsigmoid(float x) {
    return __fdividef(1.0f, 1.0f + __expf(-x));
}
__device__ __forceinline__ float ftanh(float x) {
    float e = __expf(2.0f * x);
    return 1.0f - __fdividef(2.0f, e + 1.0f);
}
__device__ __forceinline__ uint32_t f2tf(float f) {
    uint32_t u;
    asm("cvt.rna.tf32.f32 %0, %1;" : "=r"(u) : "f"(f));
    return u;
}

// ---------------------------------------------------------------------------
// TF32 MMA m16n8k8
// ---------------------------------------------------------------------------
__device__ __forceinline__ void mma_tf32(float* c, const uint32_t* a,
                                         const uint32_t* b) {
    asm volatile(
        "mma.sync.aligned.m16n8k8.row.col.f32.tf32.tf32.f32 "
        "{%0,%1,%2,%3}, {%4,%5,%6,%7}, {%8,%9}, {%0,%1,%2,%3};\n"
        : "+f"(c[0]), "+f"(c[1]), "+f"(c[2]), "+f"(c[3])
        : "r"(a[0]), "r"(a[1]), "r"(a[2]), "r"(a[3]), "r"(b[0]), "r"(b[1]));
}

// ---------------------------------------------------------------------------
// 128x128 TF32 GEMM body (NT): 256 threads, 8 warps of 64x32, BK=16 dbuf.
// Ag0 = A + bm*K, Bg0 = B + brow0*K, Cg0 = C + bm*ldc + ccol0.
// ---------------------------------------------------------------------------
__device__ __forceinline__ void gemm128x128(const float* __restrict__ Ag0,
                                            const float* __restrict__ Bg0,
                                            float* __restrict__ Cg0,
                                            int K, int ldc)
{
    __shared__ uint32_t As[2][16][136];
    __shared__ uint32_t Bs[2][128][20];

    const int tid   = threadIdx.x;
    const int lane  = tid & 31;
    const int warp  = tid >> 5;
    const int group = lane >> 2;
    const int tig   = lane & 3;
    const int wm = (warp >> 2) * 64;   // 2 warp rows
    const int wn = (warp & 3) * 32;    // 4 warp cols

    const int lr = tid >> 1;           // 0..127
    const int lk = (tid & 1) * 8;      // 0 or 8
    const float* Ag = Ag0 + (size_t)lr * K + lk;
    const float* Bg = Bg0 + (size_t)lr * K + lk;

    float c[4][4][4];
#pragma unroll
    for (int mt = 0; mt < 4; mt++)
#pragma unroll
        for (int nt = 0; nt < 4; nt++)
#pragma unroll
            for (int q = 0; q < 4; q++) c[mt][nt][q] = 0.0f;

    float4 va[2], vb[2];
#pragma unroll
    for (int h = 0; h < 2; h++) {
        va[h] = *(const float4*)(Ag + 4 * h);
        vb[h] = *(const float4*)(Bg + 4 * h);
    }
#pragma unroll
    for (int h = 0; h < 2; h++) {
        As[0][lk + 4 * h + 0][lr] = f2tf(va[h].x);
        As[0][lk + 4 * h + 1][lr] = f2tf(va[h].y);
        As[0][lk + 4 * h + 2][lr] = f2tf(va[h].z);
        As[0][lk + 4 * h + 3][lr] = f2tf(va[h].w);
        uint4 t;
        t.x = f2tf(vb[h].x); t.y = f2tf(vb[h].y);
        t.z = f2tf(vb[h].z); t.w = f2tf(vb[h].w);
        *(uint4*)&Bs[0][lr][lk + 4 * h] = t;
    }
    __syncthreads();

    int buf = 0;
    for (int k0 = 0; k0 < K; k0 += 16) {
        const bool more = (k0 + 16 < K);
        if (more) {
#pragma unroll
            for (int h = 0; h < 2; h++) {
                va[h] = *(const float4*)(Ag + k0 + 16 + 4 * h);
                vb[h] = *(const float4*)(Bg + k0 + 16 + 4 * h);
            }
        }
#pragma unroll
        for (int ks = 0; ks < 2; ks++) {
            const int kk = ks * 8;
            uint32_t a[4][4], b[4][2];
#pragma unroll
            for (int mt = 0; mt < 4; mt++) {
                int m = wm + mt * 16 + group;
                a[mt][0] = As[buf][kk + tig][m];
                a[mt][1] = As[buf][kk + tig][m + 8];
                a[mt][2] = As[buf][kk + tig + 4][m];
                a[mt][3] = As[buf][kk + tig + 4][m + 8];
            }
#pragma unroll
            for (int nt = 0; nt < 4; nt++) {
                int n = wn + nt * 8 + group;
                b[nt][0] = Bs[buf][n][kk + tig];
                b[nt][1] = Bs[buf][n][kk + tig + 4];
            }
#pragma unroll
            for (int mt = 0; mt < 4; mt++)
#pragma unroll
                for (int nt = 0; nt < 4; nt++)
                    mma_tf32(c[mt][nt], a[mt], b[nt]);
        }
        if (more) {
            buf ^= 1;
#pragma unroll
            for (int h = 0; h < 2; h++) {
                As[buf][lk + 4 * h + 0][lr] = f2tf(va[h].x);
                As[buf][lk + 4 * h + 1][lr] = f2tf(va[h].y);
                As[buf][lk + 4 * h + 2][lr] = f2tf(va[h].z);
                As[buf][lk + 4 * h + 3][lr] = f2tf(va[h].w);
                uint4 t;
                t.x = f2tf(vb[h].x); t.y = f2tf(vb[h].y);
                t.z = f2tf(vb[h].z); t.w = f2tf(vb[h].w);
                *(uint4*)&Bs[buf][lr][lk + 4 * h] = t;
            }
            __syncthreads();
        }
    }

#pragma unroll
    for (int mt = 0; mt < 4; mt++) {
        const int m0 = wm + mt * 16 + group;
#pragma unroll
        for (int nt = 0; nt < 4; nt++) {
            const int n0 = wn + nt * 8 + 2 * tig;
            *(float2*)(Cg0 + (size_t)m0 * ldc + n0) =
                make_float2(c[mt][nt][0], c[mt][nt][1]);
            *(float2*)(Cg0 + (size_t)(m0 + 8) * ldc + n0) =
                make_float2(c[mt][nt][2], c[mt][nt][3]);
        }
    }
}

__global__ void __launch_bounds__(256)
tf32_gemm_nt(const float* __restrict__ A, const float* __restrict__ B,
             float* __restrict__ C, int K, int ldc)
{
    gemm128x128(A + (size_t)blockIdx.y * 128 * K,
                B + (size_t)blockIdx.x * 128 * K,
                C + (size_t)blockIdx.y * 128 * ldc + blockIdx.x * 128,
                K, ldc);
}

// ---------------------------------------------------------------------------
// Sequential recurrence body: 128 threads, one (b,head) per block id bh.
// ---------------------------------------------------------------------------
__device__ void scan_body(const float* __restrict__ proj,
                          const float* __restrict__ xi_in,
                          const float* __restrict__ sw,
                          float* __restrict__ y, int bh)
{
    const int tid  = threadIdx.x;
    const int k    = tid & 63;
    const bool isf = tid < 64;
    const int head = bh & 7;
    const int b    = bh >> 3;

    __shared__ __align__(16) float h_sh[64];
    __shared__ __align__(16) float hr_sh[64];

    unsigned long long wg[32];  // Wf (f-threads) or Wr (r-threads)
    unsigned long long wz[32];  // W  (f-threads only)
    {
        const int gidx = isf ? (NHEADS + head) : (2 * NHEADS + head);
        const float* base = sw + (size_t)gidx * 64 * 64 + k;
#pragma unroll
        for (int i = 0; i < 32; i++)
            wg[i] = pk2(base[(2 * i) * 64], base[(2 * i + 1) * 64]);
        if (isf) {
            const float* bz = sw + (size_t)head * 64 * 64 + k;
#pragma unroll
            for (int i = 0; i < 32; i++)
                wz[i] = pk2(bz[(2 * i) * 64], bz[(2 * i + 1) * 64]);
        }
    }

    if (tid < 64) h_sh[tid] = 0.0f;
    __syncthreads();

    const float* xg_ptr = proj + (size_t)b * SEQ * PROJW
                          + (isf ? STATE : 2 * STATE) + head * HDIM + k;
    const float* xi_ptr = xi_in + (size_t)b * SEQ * STATE + head * HDIM + k;
    float* y_ptr = y + (size_t)b * SEQ * STATE + head * HDIM + k;

    float xg_buf[4], xi_buf[4];
#pragma unroll
    for (int j = 0; j < 4; j++) {
        xg_buf[j] = xg_ptr[(size_t)j * PROJW];
        xi_buf[j] = isf ? xi_ptr[(size_t)j * STATE] : 0.0f;
    }

    const ulonglong2* hp  = (const ulonglong2*)h_sh;
    const ulonglong2* hrp = (const ulonglong2*)hr_sh;

    for (int t0 = 0; t0 < SEQ; t0 += 4) {
#pragma unroll
        for (int j = 0; j < 4; j++) {
            const int t = t0 + j;
            const float xg  = xg_buf[j];
            const float xiv = xi_buf[j];
            int tp = t + 4; if (tp > SEQ - 1) tp = SEQ - 1;
            xg_buf[j] = xg_ptr[(size_t)tp * PROJW];
            if (isf) xi_buf[j] = xi_ptr[(size_t)tp * STATE];

            // phase 1: gate dot over previous h (4 chains, LDS.128 broadcast)
            unsigned long long a0 = 0ull, a1 = 0ull, a2 = 0ull, a3 = 0ull;
#pragma unroll
            for (int i = 0; i < 8; i++) {
                ulonglong2 p0 = hp[2 * i];
                ulonglong2 p1 = hp[2 * i + 1];
                fma2(a0, p0.x, wg[4 * i + 0]);
                fma2(a1, p0.y, wg[4 * i + 1]);
                fma2(a2, p1.x, wg[4 * i + 2]);
                fma2(a3, p1.y, wg[4 * i + 3]);
            }
            const float gate =
                fsigmoid(hadd2(add2(add2(a0, a1), add2(a2, a3))) + xg);
            const float hk = h_sh[k];
            if (!isf) hr_sh[k] = hk * gate;    // r-path publishes h*r
            __syncthreads();

            if (isf) {
                unsigned long long z0 = 0ull, z1 = 0ull, z2 = 0ull, z3 = 0ull;
#pragma unroll
                for (int i = 0; i < 8; i++) {
                    ulonglong2 p0 = hrp[2 * i];
                    ulonglong2 p1 = hrp[2 * i + 1];
                    fma2(z0, p0.x, wz[4 * i + 0]);
                    fma2(z1, p0.y, wz[4 * i + 1]);
                    fma2(z2, p1.x, wz[4 * i + 2]);
                    fma2(z3, p1.y, wz[4 * i + 3]);
                }
                const float z =
                    ftanh(hadd2(add2(add2(z0, z1), add2(z2, z3))) + xiv);
                const float hn = gate * hk + (1.0f - gate) * z;
                h_sh[k] = hn;
                y_ptr[(size_t)t * STATE] = hn;
            }
            __syncthreads();
        }
    }
}

// ---------------------------------------------------------------------------
// Fused: blocks 0..31 -> scan; blocks 32..543 -> g-column GEMM (cols 1536..2047)
// ---------------------------------------------------------------------------
__global__ void __launch_bounds__(256)
fused_scan_ggemm(const float* __restrict__ proj_in,
                 const float* __restrict__ xi_in,
                 const float* __restrict__ sw,
                 float* __restrict__ y,
                 const float* __restrict__ x,
                 const float* __restrict__ w_in,
                 float* __restrict__ proj_out)
{
    if (blockIdx.x < 32) {
        if (threadIdx.x >= 128) return;
        scan_body(proj_in, xi_in, sw, y, blockIdx.x);
    } else {
        const int idx = blockIdx.x - 32;
        const int bx = idx & 3;        // 4 n-tiles (512 cols)
        const int by = idx >> 2;       // 128 m-tiles
        gemm128x128(x + (size_t)by * 128 * DMODEL,
                    w_in + (size_t)(3 * STATE + bx * 128) * DMODEL,
                    proj_out + (size_t)by * 128 * PROJW + 3 * STATE + bx * 128,
                    DMODEL, PROJW);
    }
}

// ---------------------------------------------------------------------------
// Depthwise causal conv (K=4) over xi (= proj[:, :512]) + SiLU -> g_xi
// ---------------------------------------------------------------------------
__global__ void conv_silu_kernel(const float* __restrict__ proj,
                                 const float* __restrict__ cw,
                                 float* __restrict__ xi)
{
    int idx = blockIdx.x * 256 + threadIdx.x;           // over ROWS*STATE
    if (idx >= ROWS * STATE) return;
    int c   = idx & (STATE - 1);
    int row = idx >> 9;
    int s   = row & (SEQ - 1);
    float acc = 0.0f;
#pragma unroll
    for (int kk = 0; kk < 4; kk++) {
        int d = kk - 3;
        if (s + d >= 0)
            acc += cw[c * 4 + kk] * proj[(size_t)(row + d) * PROJW + c];
    }
    xi[idx] = acc * fsigmoid(acc);
}

// ---------------------------------------------------------------------------
// Epilogue: v = y * silu(g); rmsnorm over 512; * norm_w -> g_yn
// ---------------------------------------------------------------------------
__global__ void __launch_bounds__(128)
epilogue_kernel(const float* __restrict__ y, const float* __restrict__ proj,
                const float* __restrict__ norm_w, float* __restrict__ yn)
{
    const int row = blockIdx.x;
    const int tid = threadIdx.x;
    const float* yr = y    + (size_t)row * STATE;
    const float* gr = proj + (size_t)row * PROJW + 3 * STATE;

    float v[4];
    float ss = 0.0f;
#pragma unroll
    for (int q = 0; q < 4; q++) {
        int c = tid + q * 128;
        float g = gr[c];
        float val = yr[c] * g * fsigmoid(g);
        v[q] = val;
        ss += val * val;
    }
#pragma unroll
    for (int off = 16; off > 0; off >>= 1)
        ss += __shfl_xor_sync(0xffffffffu, ss, off);
    __shared__ float red[4];
    if ((tid & 31) == 0) red[tid >> 5] = ss;
    __syncthreads();
    float tot = red[0] + red[1] + red[2] + red[3];
    float scale = rsqrtf(tot * (1.0f / 512.0f) + 1e-6f);
#pragma unroll
    for (int q = 0; q < 4; q++) {
        int c = tid + q * 128;
        yn[(size_t)row * STATE + c] = v[q] * scale * norm_w[c];
    }
}

// ---------------------------------------------------------------------------
// Launch
// ---------------------------------------------------------------------------
extern "C" void kernel_launch(void* const* d_in, const int* in_sizes, int n_in,
                              void* d_out, int out_size)
{
    const float* x      = (const float*)d_in[0];
    const float* w_in   = (const float*)d_in[1];
    const float* conv_w = (const float*)d_in[2];
    const float* sw     = (const float*)d_in[3];
    const float* norm_w = (const float*)d_in[4];
    const float* w_out  = (const float*)d_in[5];
    float* out = (float*)d_out;

    float *proj, *xi, *y, *yn;
    cudaGetSymbolAddress((void**)&proj, g_proj);
    cudaGetSymbolAddress((void**)&xi,   g_xi);
    cudaGetSymbolAddress((void**)&y,    g_y);
    cudaGetSymbolAddress((void**)&yn,   g_yn);

    // 1. proj[:, 0:1536] = x @ w_in[0:1536]^T  (xi_raw | xf | xr)
    {
        dim3 grid(12, ROWS / 128);
        tf32_gemm_nt<<<grid, 256>>>(x, w_in, proj, DMODEL, PROJW);
    }
    // 2. depthwise conv + silu -> xi
    conv_silu_kernel<<<(ROWS * STATE) / 256, 256>>>(proj, conv_w, xi);
    // 3. fused: sequential recurrence (32 blocks) + g-column GEMM (512 blocks)
    fused_scan_ggemm<<<32 + 512, 256>>>(proj, xi, sw, y, x, w_in, proj);
    // 4. gate + rmsnorm -> yn
    epilogue_kernel<<<ROWS, 128>>>(y, proj, norm_w, yn);
    // 5. out = yn @ w_out^T  (16384 x 1024 x 512)
    {
        dim3 grid(DMODEL / 128, ROWS / 128);
        tf32_gemm_nt<<<grid, 256>>>(yn, w_out, out, STATE, DMODEL);
    }
}

// round 4
// speedup vs baseline: 1.7121x; 1.0968x over previous
#include <cuda_runtime.h>
#include <cuda_bf16.h>
#include <cstdint>

// ---------------------------------------------------------------------------
// Problem constants
// ---------------------------------------------------------------------------
#define BATCH   4
#define SEQ     4096
#define DMODEL  1024
#define NHEADS  8
#define HDIM    64
#define STATE   512            // NHEADS*HDIM
#define PROJW   2048           // 4*STATE
#define ROWS    (BATCH*SEQ)    // 16384

// GEMM tiling
#define BM 128
#define BN 256
#define BK 16
#define NSTAGE 3
#define A_STRIDE 20            // words per A row (16 + pad)
#define B_STRIDE 20            // words per B row
#define A_STAGE_W (BM * A_STRIDE)   // 2560 words
#define B_STAGE_W (BN * B_STRIDE)   // 5120 words
#define SMEM_DYN_BYTES (NSTAGE * (A_STAGE_W + B_STAGE_W) * 4)  // 92160

// ---------------------------------------------------------------------------
// Scratch (device globals -- no runtime allocation allowed)
// ---------------------------------------------------------------------------
__device__ float g_proj[(size_t)ROWS * PROJW];   // [xi_raw | xf | xr | g]
__device__ float g_xi  [(size_t)ROWS * STATE];   // conv+silu output
__device__ float g_y   [(size_t)ROWS * STATE];   // recurrence output
__device__ float g_yn  [(size_t)ROWS * STATE];   // gated + rmsnormed

// ---------------------------------------------------------------------------
// Helpers
// ---------------------------------------------------------------------------
__device__ __forceinline__ unsigned long long pk2(float lo, float hi) {
    unsigned long long r;
    asm("mov.b64 %0, {%1, %2};" : "=l"(r) : "f"(lo), "f"(hi));
    return r;
}
__device__ __forceinline__ void fma2(unsigned long long& d,
                                     unsigned long long a,
                                     unsigned long long b) {
    asm("fma.rn.f32x2 %0, %1, %2, %0;" : "+l"(d) : "l"(a), "l"(b));
}
__device__ __forceinline__ unsigned long long add2(unsigned long long a,
                                                   unsigned long long b) {
    unsigned long long d;
    asm("add.rn.f32x2 %0, %1, %2;" : "=l"(d) : "l"(a), "l"(b));
    return d;
}
__device__ __forceinline__ float hadd2(unsigned long long v) {
    float a, b;
    asm("mov.b64 {%0, %1}, %2;" : "=f"(a), "=f"(b) : "l"(v));
    return a + b;
}
__device__ __forceinline__ float fsigmoid(float x) {
    return __fdividef(1.0f, 1.0f + __expf(-x));
}
__device__ __forceinline__ float ftanh(float x) {
    float e = __expf(2.0f * x);
    return 1.0f - __fdividef(2.0f, e + 1.0f);
}
__device__ __forceinline__ uint32_t f2tf(float f) {
    uint32_t u;
    asm("cvt.rna.tf32.f32 %0, %1;" : "=r"(u) : "f"(f));
    return u;
}
__device__ __forceinline__ void mma_tf32(float* c, const uint32_t* a,
                                         const uint32_t* b) {
    asm volatile(
        "mma.sync.aligned.m16n8k8.row.col.f32.tf32.tf32.f32 "
        "{%0,%1,%2,%3}, {%4,%5,%6,%7}, {%8,%9}, {%0,%1,%2,%3};\n"
        : "+f"(c[0]), "+f"(c[1]), "+f"(c[2]), "+f"(c[3])
        : "r"(a[0]), "r"(a[1]), "r"(a[2]), "r"(a[3]), "r"(b[0]), "r"(b[1]));
}
__device__ __forceinline__ void cp16(uint32_t dst, const float* src) {
    asm volatile("cp.async.cg.shared.global [%0], [%1], 16;\n"
                 :: "r"(dst), "l"(src));
}

// ---------------------------------------------------------------------------
// 128x256 TF32 GEMM body (NT): 256 threads, 8 warps of 64x64, cp.async 3-stage
// C[m,n] = sum_k A[m,k]*B[n,k].  K % 16 == 0, K >= 32.
// ---------------------------------------------------------------------------
__device__ __forceinline__ void gemm_body(const float* __restrict__ Ag0,
                                          const float* __restrict__ Bg0,
                                          float* __restrict__ Cg0,
                                          int K, int ldc)
{
    extern __shared__ float smem_dyn[];
    float* As = smem_dyn;                         // [NSTAGE][BM][A_STRIDE]
    float* Bs = smem_dyn + NSTAGE * A_STAGE_W;    // [NSTAGE][BN][B_STRIDE]
    const uint32_t aBase = (uint32_t)__cvta_generic_to_shared(As);
    const uint32_t bBase = (uint32_t)__cvta_generic_to_shared(Bs);

    const int tid   = threadIdx.x;
    const int lane  = tid & 31;
    const int warp  = tid >> 5;
    const int group = lane >> 2;
    const int tig   = lane & 3;
    const int wm = (warp >> 2) * 64;   // 2 warp rows
    const int wn = (warp & 3) * 64;    // 4 warp cols

    float c[4][8][4];
#pragma unroll
    for (int mt = 0; mt < 4; mt++)
#pragma unroll
        for (int nt = 0; nt < 8; nt++)
#pragma unroll
            for (int q = 0; q < 4; q++) c[mt][nt][q] = 0.0f;

    // cp.async chunk mapping (16B chunks)
    const int arow0 = tid >> 2;              // A: cid=tid, tid+256
    const int akc   = (tid & 3) << 2;
    const int niter = K >> 4;

    auto load_stage = [&](int st, int ko) {
        const uint32_t aS = aBase + (uint32_t)(st * A_STAGE_W) * 4u;
        const uint32_t bS = bBase + (uint32_t)(st * B_STAGE_W) * 4u;
#pragma unroll
        for (int j = 0; j < 2; j++) {
            int row = arow0 + j * 64;
            cp16(aS + (uint32_t)(row * A_STRIDE + akc) * 4u,
                 Ag0 + (size_t)row * K + ko + akc);
        }
#pragma unroll
        for (int j = 0; j < 4; j++) {
            int row = arow0 + j * 64;
            cp16(bS + (uint32_t)(row * B_STRIDE + akc) * 4u,
                 Bg0 + (size_t)row * K + ko + akc);
        }
        asm volatile("cp.async.commit_group;\n");
    };

    load_stage(0, 0);
    load_stage(1, 16);

    for (int it = 0; it < niter; it++) {
        const int st = it % NSTAGE;
        asm volatile("cp.async.wait_group 1;\n");
        __syncthreads();

        const float* Ast = As + st * A_STAGE_W;
        const float* Bst = Bs + st * B_STAGE_W;
#pragma unroll
        for (int ks = 0; ks < 2; ks++) {
            const int kk = ks * 8;
            uint32_t a[4][4], b[8][2];
#pragma unroll
            for (int mt = 0; mt < 4; mt++) {
                const int m = wm + mt * 16 + group;
                a[mt][0] = f2tf(Ast[m * A_STRIDE + kk + tig]);
                a[mt][1] = f2tf(Ast[(m + 8) * A_STRIDE + kk + tig]);
                a[mt][2] = f2tf(Ast[m * A_STRIDE + kk + tig + 4]);
                a[mt][3] = f2tf(Ast[(m + 8) * A_STRIDE + kk + tig + 4]);
            }
#pragma unroll
            for (int nt = 0; nt < 8; nt++) {
                const int n = wn + nt * 8 + group;
                b[nt][0] = f2tf(Bst[n * B_STRIDE + kk + tig]);
                b[nt][1] = f2tf(Bst[n * B_STRIDE + kk + tig + 4]);
            }
#pragma unroll
            for (int mt = 0; mt < 4; mt++)
#pragma unroll
                for (int nt = 0; nt < 8; nt++)
                    mma_tf32(c[mt][nt], a[mt], b[nt]);
        }

        if (it + 2 < niter)
            load_stage((it + 2) % NSTAGE, (it + 2) * 16);
        else
            asm volatile("cp.async.commit_group;\n");   // keep group count uniform
    }

#pragma unroll
    for (int mt = 0; mt < 4; mt++) {
        const int m0 = wm + mt * 16 + group;
#pragma unroll
        for (int nt = 0; nt < 8; nt++) {
            const int n0 = wn + nt * 8 + 2 * tig;
            *(float2*)(Cg0 + (size_t)m0 * ldc + n0) =
                make_float2(c[mt][nt][0], c[mt][nt][1]);
            *(float2*)(Cg0 + (size_t)(m0 + 8) * ldc + n0) =
                make_float2(c[mt][nt][2], c[mt][nt][3]);
        }
    }
}

__global__ void __launch_bounds__(256)
tf32_gemm_nt(const float* __restrict__ A, const float* __restrict__ B,
             float* __restrict__ C, int K, int ldc)
{
    gemm_body(A + (size_t)blockIdx.y * BM * K,
              B + (size_t)blockIdx.x * BN * K,
              C + (size_t)blockIdx.y * BM * ldc + blockIdx.x * BN,
              K, ldc);
}

// ---------------------------------------------------------------------------
// Sequential recurrence body: 128 threads, one (b,head) per bh.
// ---------------------------------------------------------------------------
__device__ void scan_body(const float* __restrict__ proj,
                          const float* __restrict__ xi_in,
                          const float* __restrict__ sw,
                          float* __restrict__ y, int bh)
{
    const int tid  = threadIdx.x;
    const int k    = tid & 63;
    const bool isf = tid < 64;
    const int head = bh & 7;
    const int b    = bh >> 3;

    __shared__ __align__(16) float h_sh[64];
    __shared__ __align__(16) float hr_sh[64];

    unsigned long long wg[32];  // Wf (f-threads) or Wr (r-threads)
    unsigned long long wz[32];  // W  (f-threads only)
    {
        const int gidx = isf ? (NHEADS + head) : (2 * NHEADS + head);
        const float* base = sw + (size_t)gidx * 64 * 64 + k;
#pragma unroll
        for (int i = 0; i < 32; i++)
            wg[i] = pk2(base[(2 * i) * 64], base[(2 * i + 1) * 64]);
        if (isf) {
            const float* bz = sw + (size_t)head * 64 * 64 + k;
#pragma unroll
            for (int i = 0; i < 32; i++)
                wz[i] = pk2(bz[(2 * i) * 64], bz[(2 * i + 1) * 64]);
        }
    }

    if (tid < 64) h_sh[tid] = 0.0f;
    __syncthreads();

    const float* xg_ptr = proj + (size_t)b * SEQ * PROJW
                          + (isf ? STATE : 2 * STATE) + head * HDIM + k;
    const float* xi_ptr = xi_in + (size_t)b * SEQ * STATE + head * HDIM + k;
    float* y_ptr = y + (size_t)b * SEQ * STATE + head * HDIM + k;

    float xg_buf[4], xi_buf[4];
#pragma unroll
    for (int j = 0; j < 4; j++) {
        xg_buf[j] = xg_ptr[(size_t)j * PROJW];
        xi_buf[j] = isf ? xi_ptr[(size_t)j * STATE] : 0.0f;
    }

    const ulonglong2* hp  = (const ulonglong2*)h_sh;
    const ulonglong2* hrp = (const ulonglong2*)hr_sh;

    for (int t0 = 0; t0 < SEQ; t0 += 4) {
#pragma unroll
        for (int j = 0; j < 4; j++) {
            const int t = t0 + j;
            const float xg  = xg_buf[j];
            const float xiv = xi_buf[j];
            int tp = t + 4; if (tp > SEQ - 1) tp = SEQ - 1;
            xg_buf[j] = xg_ptr[(size_t)tp * PROJW];
            if (isf) xi_buf[j] = xi_ptr[(size_t)tp * STATE];

            unsigned long long a0 = 0ull, a1 = 0ull, a2 = 0ull, a3 = 0ull;
#pragma unroll
            for (int i = 0; i < 8; i++) {
                ulonglong2 p0 = hp[2 * i];
                ulonglong2 p1 = hp[2 * i + 1];
                fma2(a0, p0.x, wg[4 * i + 0]);
                fma2(a1, p0.y, wg[4 * i + 1]);
                fma2(a2, p1.x, wg[4 * i + 2]);
                fma2(a3, p1.y, wg[4 * i + 3]);
            }
            const float gate =
                fsigmoid(hadd2(add2(add2(a0, a1), add2(a2, a3))) + xg);
            const float hk = h_sh[k];
            if (!isf) hr_sh[k] = hk * gate;
            __syncthreads();

            if (isf) {
                unsigned long long z0 = 0ull, z1 = 0ull, z2 = 0ull, z3 = 0ull;
#pragma unroll
                for (int i = 0; i < 8; i++) {
                    ulonglong2 p0 = hrp[2 * i];
                    ulonglong2 p1 = hrp[2 * i + 1];
                    fma2(z0, p0.x, wz[4 * i + 0]);
                    fma2(z1, p0.y, wz[4 * i + 1]);
                    fma2(z2, p1.x, wz[4 * i + 2]);
                    fma2(z3, p1.y, wz[4 * i + 3]);
                }
                const float z =
                    ftanh(hadd2(add2(add2(z0, z1), add2(z2, z3))) + xiv);
                const float hn = gate * hk + (1.0f - gate) * z;
                h_sh[k] = hn;
                y_ptr[(size_t)t * STATE] = hn;
            }
            __syncthreads();
        }
    }
}

// ---------------------------------------------------------------------------
// Fused: blocks 0..31 -> scan; blocks 32.. -> g-column GEMM (cols 1536..2047)
// ---------------------------------------------------------------------------
__global__ void __launch_bounds__(256)
fused_scan_ggemm(const float* __restrict__ proj_in,
                 const float* __restrict__ xi_in,
                 const float* __restrict__ sw,
                 float* __restrict__ y,
                 const float* __restrict__ x,
                 const float* __restrict__ w_in,
                 float* __restrict__ proj_out)
{
    if (blockIdx.x < 32) {
        if (threadIdx.x >= 128) return;
        scan_body(proj_in, xi_in, sw, y, blockIdx.x);
    } else {
        const int idx = blockIdx.x - 32;
        const int bx = idx & 1;        // 2 n-tiles (512 cols)
        const int by = idx >> 1;       // 128 m-tiles
        gemm_body(x + (size_t)by * BM * DMODEL,
                  w_in + (size_t)(3 * STATE + bx * BN) * DMODEL,
                  proj_out + (size_t)by * BM * PROJW + 3 * STATE + bx * BN,
                  DMODEL, PROJW);
    }
}

// ---------------------------------------------------------------------------
// Depthwise causal conv (K=4) over xi (= proj[:, :512]) + SiLU -> g_xi
// ---------------------------------------------------------------------------
__global__ void conv_silu_kernel(const float* __restrict__ proj,
                                 const float* __restrict__ cw,
                                 float* __restrict__ xi)
{
    int idx = blockIdx.x * 256 + threadIdx.x;           // over ROWS*STATE
    if (idx >= ROWS * STATE) return;
    int c   = idx & (STATE - 1);
    int row = idx >> 9;
    int s   = row & (SEQ - 1);
    float acc = 0.0f;
#pragma unroll
    for (int kk = 0; kk < 4; kk++) {
        int d = kk - 3;
        if (s + d >= 0)
            acc += cw[c * 4 + kk] * proj[(size_t)(row + d) * PROJW + c];
    }
    xi[idx] = acc * fsigmoid(acc);
}

// ---------------------------------------------------------------------------
// Epilogue: v = y * silu(g); rmsnorm over 512; * norm_w -> g_yn
// ---------------------------------------------------------------------------
__global__ void __launch_bounds__(128)
epilogue_kernel(const float* __restrict__ y, const float* __restrict__ proj,
                const float* __restrict__ norm_w, float* __restrict__ yn)
{
    const int row = blockIdx.x;
    const int tid = threadIdx.x;
    const float* yr = y    + (size_t)row * STATE;
    const float* gr = proj + (size_t)row * PROJW + 3 * STATE;

    float v[4];
    float ss = 0.0f;
#pragma unroll
    for (int q = 0; q < 4; q++) {
        int c = tid + q * 128;
        float g = gr[c];
        float val = yr[c] * g * fsigmoid(g);
        v[q] = val;
        ss += val * val;
    }
#pragma unroll
    for (int off = 16; off > 0; off >>= 1)
        ss += __shfl_xor_sync(0xffffffffu, ss, off);
    __shared__ float red[4];
    if ((tid & 31) == 0) red[tid >> 5] = ss;
    __syncthreads();
    float tot = red[0] + red[1] + red[2] + red[3];
    float scale = rsqrtf(tot * (1.0f / 512.0f) + 1e-6f);
#pragma unroll
    for (int q = 0; q < 4; q++) {
        int c = tid + q * 128;
        yn[(size_t)row * STATE + c] = v[q] * scale * norm_w[c];
    }
}

// ---------------------------------------------------------------------------
// Launch
// ---------------------------------------------------------------------------
extern "C" void kernel_launch(void* const* d_in, const int* in_sizes, int n_in,
                              void* d_out, int out_size)
{
    const float* x      = (const float*)d_in[0];
    const float* w_in   = (const float*)d_in[1];
    const float* conv_w = (const float*)d_in[2];
    const float* sw     = (const float*)d_in[3];
    const float* norm_w = (const float*)d_in[4];
    const float* w_out  = (const float*)d_in[5];
    float* out = (float*)d_out;

    float *proj, *xi, *y, *yn;
    cudaGetSymbolAddress((void**)&proj, g_proj);
    cudaGetSymbolAddress((void**)&xi,   g_xi);
    cudaGetSymbolAddress((void**)&y,    g_y);
    cudaGetSymbolAddress((void**)&yn,   g_yn);

    cudaFuncSetAttribute(tf32_gemm_nt,
                         cudaFuncAttributeMaxDynamicSharedMemorySize,
                         SMEM_DYN_BYTES);
    cudaFuncSetAttribute(fused_scan_ggemm,
                         cudaFuncAttributeMaxDynamicSharedMemorySize,
                         SMEM_DYN_BYTES);

    // 1. proj[:, 0:1536] = x @ w_in[0:1536]^T  (xi_raw | xf | xr)
    {
        dim3 grid(6, ROWS / BM);   // 6 n-tiles of 256 = 1536 cols
        tf32_gemm_nt<<<grid, 256, SMEM_DYN_BYTES>>>(x, w_in, proj,
                                                    DMODEL, PROJW);
    }
    // 2. depthwise conv + silu -> xi
    conv_silu_kernel<<<(ROWS * STATE) / 256, 256>>>(proj, conv_w, xi);
    // 3. fused: sequential recurrence (32 blocks) + g-column GEMM (256 blocks)
    fused_scan_ggemm<<<32 + 2 * (ROWS / BM), 256, SMEM_DYN_BYTES>>>(
        proj, xi, sw, y, x, w_in, proj);
    // 4. gate + rmsnorm -> yn
    epilogue_kernel<<<ROWS, 128>>>(y, proj, norm_w, yn);
    // 5. out = yn @ w_out^T  (16384 x 1024 x 512)
    {
        dim3 grid(DMODEL / BN, ROWS / BM);  // 4 x 128
        tf32_gemm_nt<<<grid, 256, SMEM_DYN_BYTES>>>(yn, w_out, out,
                                                    STATE, DMODEL);
    }
}